// round 2
// baseline (speedup 1.0000x reference)
#include <cuda_runtime.h>

#define NN 100000
#define NE 1600000

// ---------------- scratch (static device globals; no allocation) ----------------
__device__ int   g_cnt[NN];
__device__ int   g_roff[NN + 1];
__device__ int   g_csrc[NE];
__device__ int   g_bsum[128];
__device__ float g_dinv[NN];
__device__ float g_as[NN * 4];
__device__ float g_ad[NN * 4];
__device__ float g_t0[NN * 64];
__device__ float g_ha[NN * 64];
__device__ float g_hb[NN * 64];

// ---------------- CSR build ----------------
__global__ void deg_kernel(const int* __restrict__ dst, int e) {
    int i = blockIdx.x * blockDim.x + threadIdx.x;
    if (i < e) atomicAdd(&g_cnt[dst[i]], 1);
}

__global__ void scan1_kernel(int n) {
    __shared__ int wsum[32];
    int i = blockIdx.x * 1024 + threadIdx.x;
    int lane = threadIdx.x & 31, wid = threadIdx.x >> 5;
    int v = (i < n) ? g_cnt[i] : 0;
    int s = v;
#pragma unroll
    for (int o = 1; o < 32; o <<= 1) {
        int t = __shfl_up_sync(0xffffffffu, s, o);
        if (lane >= o) s += t;
    }
    if (lane == 31) wsum[wid] = s;
    __syncthreads();
    if (wid == 0) {
        int ws = wsum[lane];
#pragma unroll
        for (int o = 1; o < 32; o <<= 1) {
            int t = __shfl_up_sync(0xffffffffu, ws, o);
            if (lane >= o) ws += t;
        }
        wsum[lane] = ws;
    }
    __syncthreads();
    if (wid > 0) s += wsum[wid - 1];
    if (i < n) g_roff[i + 1] = s;
    if (i == 0) g_roff[0] = 0;
    if (threadIdx.x == 1023) g_bsum[blockIdx.x] = s;
}

__global__ void scan2_kernel(int nb) {
    __shared__ int wsum[4];
    int lane = threadIdx.x & 31, wid = threadIdx.x >> 5;
    int v = (threadIdx.x < nb) ? g_bsum[threadIdx.x] : 0;
    int s = v;
#pragma unroll
    for (int o = 1; o < 32; o <<= 1) {
        int t = __shfl_up_sync(0xffffffffu, s, o);
        if (lane >= o) s += t;
    }
    if (lane == 31) wsum[wid] = s;
    __syncthreads();
    int add = 0;
    for (int w = 0; w < wid; w++) add += wsum[w];
    s += add;
    if (threadIdx.x < nb) g_bsum[threadIdx.x] = s;
}

__global__ void scan3_kernel(int n) {
    int i = blockIdx.x * 1024 + threadIdx.x;
    if (blockIdx.x > 0 && i < n) g_roff[i + 1] += g_bsum[blockIdx.x - 1];
}

__global__ void fill_kernel(const int* __restrict__ src, const int* __restrict__ dst, int e) {
    int i = blockIdx.x * blockDim.x + threadIdx.x;
    if (i < e) {
        int d = dst[i];
        int p = g_roff[d] + atomicAdd(&g_cnt[d], 1);
        g_csrc[p] = src[i];
    }
}

__global__ void dinv_kernel(int n) {
    int v = blockIdx.x * blockDim.x + threadIdx.x;
    if (v < n) {
        int deg = g_roff[v + 1] - g_roff[v] + 1;  // +1 self loop
        g_dinv[v] = rsqrtf((float)deg);
    }
}

// ---------------- dense matmul: Y[n,OUT] = X[n,IN] @ W[IN,OUT] ----------------
template <int IN, int OUT>
__global__ void __launch_bounds__(128) mm_kernel(const float* __restrict__ X,
                                                 const float* __restrict__ W,
                                                 float* __restrict__ Y, int n) {
    constexpr int TPR = OUT / 4;      // threads per row
    constexpr int R = 128 / TPR;      // rows per block
    __shared__ __align__(16) float Ws[IN * OUT];
    __shared__ __align__(16) float Xs[R * IN];

    for (int i = threadIdx.x; i < IN * OUT / 4; i += 128)
        ((float4*)Ws)[i] = ((const float4*)W)[i];

    int row0 = blockIdx.x * R;
    for (int i = threadIdx.x; i < R * IN / 4; i += 128) {
        int r = i / (IN / 4);
        int k4 = i % (IN / 4);
        int row = row0 + r;
        float4 val = make_float4(0.f, 0.f, 0.f, 0.f);
        if (row < n) val = ((const float4*)(X + (size_t)row * IN))[k4];
        ((float4*)Xs)[i] = val;
    }
    __syncthreads();

    int r = threadIdx.x / TPR;
    int cg = threadIdx.x % TPR;
    int row = row0 + r;
    float a0 = 0.f, a1 = 0.f, a2 = 0.f, a3 = 0.f;
    const float4* Ws4 = (const float4*)Ws;
#pragma unroll 8
    for (int k = 0; k < IN; k++) {
        float xv = Xs[r * IN + k];
        float4 w = Ws4[k * TPR + cg];
        a0 += xv * w.x; a1 += xv * w.y; a2 += xv * w.z; a3 += xv * w.w;
    }
    if (row < n)
        ((float4*)(Y + (size_t)row * OUT))[cg] = make_float4(a0, a1, a2, a3);
}

// ---------------- GCN aggregation: warp per node ----------------
template <int C>
__global__ void __launch_bounds__(256) gcn_agg(const float* __restrict__ h,
                                               const float* __restrict__ bias,
                                               const float* __restrict__ res,
                                               float* __restrict__ out, int n) {
    int v = (blockIdx.x * blockDim.x + threadIdx.x) >> 5;
    int lane = threadIdx.x & 31;
    if (v >= n) return;
    constexpr int J = C / 32;
    float dv = g_dinv[v];
    float acc[J];
#pragma unroll
    for (int j = 0; j < J; j++) acc[j] = dv * h[(size_t)v * C + lane + 32 * j];

    int e0 = g_roff[v], e1 = g_roff[v + 1];
    for (int e = e0; e < e1; e++) {
        int u = g_csrc[e];
        float w = g_dinv[u];
#pragma unroll
        for (int j = 0; j < J; j++) acc[j] += w * h[(size_t)u * C + lane + 32 * j];
    }
#pragma unroll
    for (int j = 0; j < J; j++) {
        int c = lane + 32 * j;
        float o = fmaxf(dv * acc[j] + bias[c], 0.f);
        if (res) o += res[(size_t)v * C + c];
        out[(size_t)v * C + c] = o;
    }
}

// ---------------- GAT attention scalars ----------------
__global__ void att_kernel(const float* __restrict__ hg,
                           const float* __restrict__ att_src,
                           const float* __restrict__ att_dst, int n) {
    int i = blockIdx.x * blockDim.x + threadIdx.x;
    if (i >= n * 4) return;
    int v = i >> 2, hh = i & 3;
    const float* hp = hg + (size_t)v * 64 + hh * 16;
    float s = 0.f, d = 0.f;
#pragma unroll
    for (int c = 0; c < 16; c++) {
        float x = hp[c];
        s += x * att_src[hh * 16 + c];
        d += x * att_dst[hh * 16 + c];
    }
    g_as[i] = s;
    g_ad[i] = d;
}

__device__ __forceinline__ float leakyr(float x) { return x > 0.f ? x : 0.2f * x; }

// ---------------- GAT aggregation: warp per node, online softmax ----------------
__global__ void __launch_bounds__(256) gat_agg(const float* __restrict__ hg,
                                               const float* __restrict__ bias,
                                               float* __restrict__ out, int n) {
    int v = (blockIdx.x * blockDim.x + threadIdx.x) >> 5;
    int lane = threadIdx.x & 31;
    if (v >= n) return;
    int hA = lane >> 4;        // head for channel c0 = lane
    int hB = 2 + (lane >> 4);  // head for channel c1 = lane + 32

    float adA = g_ad[v * 4 + hA], adB = g_ad[v * 4 + hB];
    float h0 = hg[(size_t)v * 64 + lane];
    float h1 = hg[(size_t)v * 64 + lane + 32];

    // self-loop initializes the online softmax
    float mA = leakyr(g_as[v * 4 + hA] + adA);
    float mB = leakyr(g_as[v * 4 + hB] + adB);
    float dA = 1.f, dB = 1.f;
    float a0 = h0, a1 = h1;

    int e0 = g_roff[v], e1 = g_roff[v + 1];
    for (int e = e0; e < e1; e++) {
        int u = g_csrc[e];
        float sA = leakyr(g_as[u * 4 + hA] + adA);
        float sB = leakyr(g_as[u * 4 + hB] + adB);
        float g0 = hg[(size_t)u * 64 + lane];
        float g1 = hg[(size_t)u * 64 + lane + 32];

        float mA2 = fmaxf(mA, sA);
        float scA = __expf(mA - mA2);
        float pA = __expf(sA - mA2);
        a0 = a0 * scA + pA * g0;
        dA = dA * scA + pA;
        mA = mA2;

        float mB2 = fmaxf(mB, sB);
        float scB = __expf(mB - mB2);
        float pB = __expf(sB - mB2);
        a1 = a1 * scB + pB * g1;
        dB = dB * scB + pB;
        mB = mB2;
    }
    out[(size_t)v * 64 + lane]      = fmaxf(a0 / dA + bias[lane], 0.f);
    out[(size_t)v * 64 + lane + 32] = fmaxf(a1 / dB + bias[lane + 32], 0.f);
}

// ---------------- final linear head ----------------
__global__ void __launch_bounds__(256) final_kernel(const float* __restrict__ h,
                                                    const float* __restrict__ Wl,
                                                    const float* __restrict__ bl,
                                                    float* __restrict__ out, int n) {
    int v = (blockIdx.x * blockDim.x + threadIdx.x) >> 5;
    int lane = threadIdx.x & 31;
    if (v >= n) return;
    float p = h[(size_t)v * 64 + lane] * Wl[lane] +
              h[(size_t)v * 64 + lane + 32] * Wl[lane + 32];
#pragma unroll
    for (int o = 16; o; o >>= 1) p += __shfl_down_sync(0xffffffffu, p, o);
    if (lane == 0) out[v] = fmaxf(p + bl[0], 0.f);
}

// ---------------- launch ----------------
extern "C" void kernel_launch(void* const* d_in, const int* in_sizes, int n_in,
                              void* d_out, int out_size) {
    const float* x   = (const float*)d_in[0];
    const int*   ei  = (const int*)d_in[1];
    const float* W1  = (const float*)d_in[2];
    const float* b1  = (const float*)d_in[3];
    const float* W2  = (const float*)d_in[4];
    const float* b2  = (const float*)d_in[5];
    const float* W3  = (const float*)d_in[6];
    const float* b3  = (const float*)d_in[7];
    const float* Wg  = (const float*)d_in[8];
    const float* ats = (const float*)d_in[9];
    const float* atd = (const float*)d_in[10];
    const float* bg  = (const float*)d_in[11];
    const float* Wl  = (const float*)d_in[12];
    const float* bl  = (const float*)d_in[13];
    float* out = (float*)d_out;

    int n = in_sizes[0] / 128;   // 100000
    int e = in_sizes[1] / 2;     // 1600000
    const int* src = ei;
    const int* dst = ei + e;

    void* p;
    int* cnt_ptr; cudaGetSymbolAddress(&p, g_cnt); cnt_ptr = (int*)p;
    float *t0, *ha, *hb;
    cudaGetSymbolAddress(&p, g_t0); t0 = (float*)p;
    cudaGetSymbolAddress(&p, g_ha); ha = (float*)p;
    cudaGetSymbolAddress(&p, g_hb); hb = (float*)p;

    int nb = (n + 1023) / 1024;
    int gE = (e + 255) / 256;
    int gN = (n + 255) / 256;
    int gW = (n * 32 + 255) / 256;  // warp-per-node kernels

    // CSR build
    cudaMemsetAsync(cnt_ptr, 0, sizeof(int) * NN, 0);
    deg_kernel<<<gE, 256>>>(dst, e);
    scan1_kernel<<<nb, 1024>>>(n);
    scan2_kernel<<<1, 128>>>(nb);
    scan3_kernel<<<nb, 1024>>>(n);
    cudaMemsetAsync(cnt_ptr, 0, sizeof(int) * NN, 0);
    fill_kernel<<<gE, 256>>>(src, dst, e);
    dinv_kernel<<<gN, 256>>>(n);

    // layer 1: GCN 128->32
    mm_kernel<128, 32><<<(n + 15) / 16, 128>>>(x, W1, t0, n);
    gcn_agg<32><<<gW, 256>>>(t0, b1, nullptr, ha, n);            // ha = h1 [N,32]

    // layer 2: GCN 32->64
    mm_kernel<32, 64><<<(n + 7) / 8, 128>>>(ha, W2, t0, n);
    gcn_agg<64><<<gW, 256>>>(t0, b2, nullptr, hb, n);            // hb = h2 [N,64]

    // layer 3: GAT 64->64
    mm_kernel<64, 64><<<(n + 7) / 8, 128>>>(hb, Wg, t0, n);
    att_kernel<<<(n * 4 + 255) / 256, 256>>>(t0, ats, atd, n);
    gat_agg<<<gW, 256>>>(t0, bg, ha, n);                         // ha = h3

    // layer 4: GCN 64->64 with residual
    mm_kernel<64, 64><<<(n + 7) / 8, 128>>>(ha, W3, t0, n);
    gcn_agg<64><<<gW, 256>>>(t0, b3, ha, hb, n);                 // hb = h4 = h3 + relu(gcn)

    // layer 5: GAT 64->64
    mm_kernel<64, 64><<<(n + 7) / 8, 128>>>(hb, Wg, t0, n);
    att_kernel<<<(n * 4 + 255) / 256, 256>>>(t0, ats, atd, n);
    gat_agg<<<gW, 256>>>(t0, bg, ha, n);                         // ha = h5

    // head
    final_kernel<<<gW, 256>>>(ha, Wl, bl, out, n);
}

// round 3
// speedup vs baseline: 1.4523x; 1.4523x over previous
#include <cuda_runtime.h>

#define NN 100000
#define NE 1600000
#define FULL 0xffffffffu

// ---------------- scratch ----------------
__device__ int   g_cnt[NN];
__device__ int   g_roff[NN + 1];
__device__ int   g_woff[NN + 1];
__device__ int   g_csrc[NE];
__device__ int   g_bsum[128];
__device__ float g_dinv[NN];
__device__ float g_as[NN * 4];
__device__ float g_ad[NN * 4];
__device__ float g_t0[NN * 64];
__device__ float g_ha[NN * 64];
__device__ float g_hb[NN * 64];

// ---------------- CSR build ----------------
__global__ void deg_kernel(const int* __restrict__ dst, int e) {
    int i = blockIdx.x * blockDim.x + threadIdx.x;
    if (i < e) atomicAdd(&g_cnt[dst[i]], 1);
}

__global__ void scan1_kernel(int n) {
    __shared__ int wsum[32];
    int i = blockIdx.x * 1024 + threadIdx.x;
    int lane = threadIdx.x & 31, wid = threadIdx.x >> 5;
    int v = (i < n) ? g_cnt[i] : 0;
    if (i < n) g_dinv[i] = rsqrtf((float)(v + 1));   // degree incl. self-loop
    int s = v;
#pragma unroll
    for (int o = 1; o < 32; o <<= 1) {
        int t = __shfl_up_sync(FULL, s, o);
        if (lane >= o) s += t;
    }
    if (lane == 31) wsum[wid] = s;
    __syncthreads();
    if (wid == 0) {
        int ws = wsum[lane];
#pragma unroll
        for (int o = 1; o < 32; o <<= 1) {
            int t = __shfl_up_sync(FULL, ws, o);
            if (lane >= o) ws += t;
        }
        wsum[lane] = ws;
    }
    __syncthreads();
    if (wid > 0) s += wsum[wid - 1];
    if (i < n) g_roff[i + 1] = s;
    if (i == 0) g_roff[0] = 0;
    if (threadIdx.x == 1023) g_bsum[blockIdx.x] = s;
}

__global__ void scan2_kernel(int nb) {
    __shared__ int wsum[4];
    int lane = threadIdx.x & 31, wid = threadIdx.x >> 5;
    int v = (threadIdx.x < nb) ? g_bsum[threadIdx.x] : 0;
    int s = v;
#pragma unroll
    for (int o = 1; o < 32; o <<= 1) {
        int t = __shfl_up_sync(FULL, s, o);
        if (lane >= o) s += t;
    }
    if (lane == 31) wsum[wid] = s;
    __syncthreads();
    int add = 0;
    for (int w = 0; w < wid; w++) add += wsum[w];
    s += add;
    if (threadIdx.x < nb) g_bsum[threadIdx.x] = s;
}

__global__ void scan3_kernel(int n) {
    int i = blockIdx.x * 1024 + threadIdx.x;
    if (i < n) {
        int add = (blockIdx.x > 0) ? g_bsum[blockIdx.x - 1] : 0;
        int val = g_roff[i + 1] + add;
        g_roff[i + 1] = val;
        g_woff[i + 1] = val;
        if (i == 0) g_woff[0] = 0;
    }
}

__global__ void fill_kernel(const int* __restrict__ src, const int* __restrict__ dst, int e) {
    int i = blockIdx.x * blockDim.x + threadIdx.x;
    if (i < e) {
        int d = dst[i];
        int p = atomicAdd(&g_woff[d], 1);
        g_csrc[p] = src[i];
    }
}

// ---------------- dense matmul: Y = X @ W, 2 rows/thread ----------------
// MODE: 0 = plain, 1 = prescale rows by g_dinv (GCN), 2 = GAT att epilogue
template <int IN, int OUT, int MODE>
__global__ void __launch_bounds__(128) mm_kernel(const float* __restrict__ X,
                                                 const float* __restrict__ W,
                                                 float* __restrict__ Y, int n,
                                                 const float* __restrict__ ats,
                                                 const float* __restrict__ atd) {
    constexpr int TPR = OUT / 4;        // threads per row
    constexpr int NR  = 128 / TPR;      // thread-rows per block
    constexpr int RPB = NR * 2;         // rows per block (2 rows / thread)
    __shared__ __align__(16) float Ws[IN * OUT];
    __shared__ __align__(16) float Xs[RPB * IN];

    for (int i = threadIdx.x; i < IN * OUT / 4; i += 128)
        ((float4*)Ws)[i] = ((const float4*)W)[i];

    int row0 = blockIdx.x * RPB;
    for (int i = threadIdx.x; i < RPB * IN / 4; i += 128) {
        int r = i / (IN / 4);
        int k4 = i % (IN / 4);
        int row = row0 + r;
        float4 val = make_float4(0.f, 0.f, 0.f, 0.f);
        if (row < n) val = ((const float4*)(X + (size_t)row * IN))[k4];
        ((float4*)Xs)[i] = val;
    }
    __syncthreads();

    int tr = threadIdx.x / TPR;
    int cg = threadIdx.x % TPR;
    int rA = 2 * tr, rB = 2 * tr + 1;
    float4 a0 = make_float4(0.f, 0.f, 0.f, 0.f);
    float4 a1 = make_float4(0.f, 0.f, 0.f, 0.f);
    const float4* Ws4 = (const float4*)Ws;
#pragma unroll 16
    for (int k = 0; k < IN; k++) {
        float x0 = Xs[rA * IN + k];
        float x1 = Xs[rB * IN + k];
        float4 w = Ws4[k * TPR + cg];
        a0.x += x0 * w.x; a0.y += x0 * w.y; a0.z += x0 * w.z; a0.w += x0 * w.w;
        a1.x += x1 * w.x; a1.y += x1 * w.y; a1.z += x1 * w.z; a1.w += x1 * w.w;
    }

    int rowA = row0 + rA, rowB = row0 + rB;
    if (MODE == 1) {
        if (rowA < n) {
            float s = g_dinv[rowA];
            a0.x *= s; a0.y *= s; a0.z *= s; a0.w *= s;
        }
        if (rowB < n) {
            float s = g_dinv[rowB];
            a1.x *= s; a1.y *= s; a1.z *= s; a1.w *= s;
        }
    }
    if (rowA < n) ((float4*)(Y + (size_t)rowA * OUT))[cg] = a0;
    if (rowB < n) ((float4*)(Y + (size_t)rowB * OUT))[cg] = a1;

    if (MODE == 2) {
        // attention projections: head = cg/4, local channel block = (cg%4)*4
        int head = cg >> 2;
        float4 av = ((const float4*)ats)[head * 4 + (cg & 3)];
        float4 dv = ((const float4*)atd)[head * 4 + (cg & 3)];
        float ps0 = a0.x * av.x + a0.y * av.y + a0.z * av.z + a0.w * av.w;
        float pd0 = a0.x * dv.x + a0.y * dv.y + a0.z * dv.z + a0.w * dv.w;
        float ps1 = a1.x * av.x + a1.y * av.y + a1.z * av.z + a1.w * av.w;
        float pd1 = a1.x * dv.x + a1.y * dv.y + a1.z * dv.z + a1.w * dv.w;
        ps0 += __shfl_down_sync(FULL, ps0, 2, 4); ps0 += __shfl_down_sync(FULL, ps0, 1, 4);
        pd0 += __shfl_down_sync(FULL, pd0, 2, 4); pd0 += __shfl_down_sync(FULL, pd0, 1, 4);
        ps1 += __shfl_down_sync(FULL, ps1, 2, 4); ps1 += __shfl_down_sync(FULL, ps1, 1, 4);
        pd1 += __shfl_down_sync(FULL, pd1, 2, 4); pd1 += __shfl_down_sync(FULL, pd1, 1, 4);
        if ((cg & 3) == 0) {
            if (rowA < n) { g_as[rowA * 4 + head] = ps0; g_ad[rowA * 4 + head] = pd0; }
            if (rowB < n) { g_as[rowB * 4 + head] = ps1; g_ad[rowB * 4 + head] = pd1; }
        }
    }
}

// ---------------- GCN aggregation (input pre-scaled by dinv[u]) ----------------
__global__ void __launch_bounds__(256) gcn_agg32(const float* __restrict__ h,
                                                 const float* __restrict__ bias,
                                                 float* __restrict__ out, int n) {
    int v = (blockIdx.x * blockDim.x + threadIdx.x) >> 5;
    int lane = threadIdx.x & 31;
    if (v >= n) return;
    float dv = g_dinv[v];
    float acc = h[(size_t)v * 32 + lane];   // self term: dinv_v * h_v already
    int e0 = g_roff[v], e1 = g_roff[v + 1];
    for (int e = e0; e < e1; e++) {
        int u = g_csrc[e];
        acc += h[(size_t)u * 32 + lane];
    }
    out[(size_t)v * 32 + lane] = fmaxf(dv * acc + bias[lane], 0.f);
}

__global__ void __launch_bounds__(256) gcn_agg64(const float* __restrict__ h,
                                                 const float* __restrict__ bias,
                                                 const float* __restrict__ res,
                                                 float* __restrict__ out, int n) {
    int v = (blockIdx.x * blockDim.x + threadIdx.x) >> 5;
    int lane = threadIdx.x & 31;
    if (v >= n) return;
    const float2* h2 = (const float2*)h;
    float dv = g_dinv[v];
    float2 acc = h2[(size_t)v * 32 + lane];
    int e0 = g_roff[v], e1 = g_roff[v + 1];
    for (int e = e0; e < e1; e++) {
        int u = g_csrc[e];
        float2 hu = h2[(size_t)u * 32 + lane];
        acc.x += hu.x; acc.y += hu.y;
    }
    float2 b2 = ((const float2*)bias)[lane];
    float2 o;
    o.x = fmaxf(dv * acc.x + b2.x, 0.f);
    o.y = fmaxf(dv * acc.y + b2.y, 0.f);
    if (res) {
        float2 r2 = ((const float2*)res)[(size_t)v * 32 + lane];
        o.x += r2.x; o.y += r2.y;
    }
    ((float2*)out)[(size_t)v * 32 + lane] = o;
}

// ---------------- GAT ----------------
__device__ __forceinline__ float leakyr(float x) { return x > 0.f ? x : 0.2f * x; }
__device__ __forceinline__ float sel4(float4 v, int h) {
    float a = (h & 1) ? v.y : v.x;
    float b = (h & 1) ? v.w : v.z;
    return (h & 2) ? b : a;
}

template <bool FINAL>
__global__ void __launch_bounds__(256) gat_agg(const float* __restrict__ hg,
                                               const float* __restrict__ bias,
                                               float* __restrict__ out,
                                               const float* __restrict__ Wl,
                                               const float* __restrict__ bl, int n) {
    int v = (blockIdx.x * blockDim.x + threadIdx.x) >> 5;
    int lane = threadIdx.x & 31;
    if (v >= n) return;
    int hh = lane >> 3;                     // head owning channels {2lane, 2lane+1}
    const float2* h2 = (const float2*)hg;
    const float4* as4 = (const float4*)g_as;
    const float4* ad4p = (const float4*)g_ad;

    float4 asv = as4[v];
    float4 adv = ad4p[v];
    int e0 = g_roff[v], e1 = g_roff[v + 1];

    // ---- pass 1: per-head max (lane-parallel over edges) ----
    float4 m4;
    m4.x = leakyr(asv.x + adv.x);
    m4.y = leakyr(asv.y + adv.y);
    m4.z = leakyr(asv.z + adv.z);
    m4.w = leakyr(asv.w + adv.w);
    for (int e = e0 + lane; e < e1; e += 32) {
        int u = g_csrc[e];
        float4 au = as4[u];
        m4.x = fmaxf(m4.x, leakyr(au.x + adv.x));
        m4.y = fmaxf(m4.y, leakyr(au.y + adv.y));
        m4.z = fmaxf(m4.z, leakyr(au.z + adv.z));
        m4.w = fmaxf(m4.w, leakyr(au.w + adv.w));
    }
#pragma unroll
    for (int o = 16; o; o >>= 1) {
        m4.x = fmaxf(m4.x, __shfl_xor_sync(FULL, m4.x, o));
        m4.y = fmaxf(m4.y, __shfl_xor_sync(FULL, m4.y, o));
        m4.z = fmaxf(m4.z, __shfl_xor_sync(FULL, m4.z, o));
        m4.w = fmaxf(m4.w, __shfl_xor_sync(FULL, m4.w, o));
    }
    float mx = sel4(m4, hh);
    float advh = sel4(adv, hh);

    // ---- pass 2: exp + weighted accumulate (1 exp/edge) ----
    float pself = __expf(leakyr(sel4(asv, hh) + advh) - mx);
    float2 hv = h2[(size_t)v * 32 + lane];
    float2 acc; acc.x = pself * hv.x; acc.y = pself * hv.y;
    float den = pself;
    for (int e = e0; e < e1; e++) {
        int u = g_csrc[e];
        float4 au = as4[u];
        float p = __expf(leakyr(sel4(au, hh) + advh) - mx);
        float2 hu = h2[(size_t)u * 32 + lane];
        acc.x += p * hu.x; acc.y += p * hu.y;
        den += p;
    }
    float inv = 1.f / den;
    float2 b2 = ((const float2*)bias)[lane];
    float2 o;
    o.x = fmaxf(acc.x * inv + b2.x, 0.f);
    o.y = fmaxf(acc.y * inv + b2.y, 0.f);

    if (FINAL) {
        float2 wl = ((const float2*)Wl)[lane];
        float p = o.x * wl.x + o.y * wl.y;
#pragma unroll
        for (int s = 16; s; s >>= 1) p += __shfl_xor_sync(FULL, p, s);
        if (lane == 0) out[v] = fmaxf(p + bl[0], 0.f);
    } else {
        ((float2*)out)[(size_t)v * 32 + lane] = o;
    }
}

// ---------------- launch ----------------
extern "C" void kernel_launch(void* const* d_in, const int* in_sizes, int n_in,
                              void* d_out, int out_size) {
    const float* x   = (const float*)d_in[0];
    const int*   ei  = (const int*)d_in[1];
    const float* W1  = (const float*)d_in[2];
    const float* b1  = (const float*)d_in[3];
    const float* W2  = (const float*)d_in[4];
    const float* b2  = (const float*)d_in[5];
    const float* W3  = (const float*)d_in[6];
    const float* b3  = (const float*)d_in[7];
    const float* Wg  = (const float*)d_in[8];
    const float* ats = (const float*)d_in[9];
    const float* atd = (const float*)d_in[10];
    const float* bg  = (const float*)d_in[11];
    const float* Wl  = (const float*)d_in[12];
    const float* bl  = (const float*)d_in[13];
    float* out = (float*)d_out;

    int n = in_sizes[0] / 128;   // 100000
    int e = in_sizes[1] / 2;     // 1600000
    const int* src = ei;
    const int* dst = ei + e;

    void* p;
    int* cnt_ptr; cudaGetSymbolAddress(&p, g_cnt); cnt_ptr = (int*)p;
    float *t0, *ha, *hb;
    cudaGetSymbolAddress(&p, g_t0); t0 = (float*)p;
    cudaGetSymbolAddress(&p, g_ha); ha = (float*)p;
    cudaGetSymbolAddress(&p, g_hb); hb = (float*)p;

    int nb = (n + 1023) / 1024;
    int gE = (e + 255) / 256;
    int gW = (n * 32 + 255) / 256;

    // CSR build
    cudaMemsetAsync(cnt_ptr, 0, sizeof(int) * NN, 0);
    deg_kernel<<<gE, 256>>>(dst, e);
    scan1_kernel<<<nb, 1024>>>(n);
    scan2_kernel<<<1, 128>>>(nb);
    scan3_kernel<<<nb, 1024>>>(n);
    fill_kernel<<<gE, 256>>>(src, dst, e);

    // layer 1: GCN 128->32
    mm_kernel<128, 32, 1><<<(n + 31) / 32, 128>>>(x, W1, t0, n, nullptr, nullptr);
    gcn_agg32<<<gW, 256>>>(t0, b1, ha, n);

    // layer 2: GCN 32->64
    mm_kernel<32, 64, 1><<<(n + 15) / 16, 128>>>(ha, W2, t0, n, nullptr, nullptr);
    gcn_agg64<<<gW, 256>>>(t0, b2, nullptr, hb, n);

    // layer 3: GAT 64->64
    mm_kernel<64, 64, 2><<<(n + 15) / 16, 128>>>(hb, Wg, t0, n, ats, atd);
    gat_agg<false><<<gW, 256>>>(t0, bg, ha, nullptr, nullptr, n);

    // layer 4: GCN 64->64 + residual
    mm_kernel<64, 64, 1><<<(n + 15) / 16, 128>>>(ha, W3, t0, n, nullptr, nullptr);
    gcn_agg64<<<gW, 256>>>(t0, b3, ha, hb, n);

    // layer 5: GAT 64->64 fused with final head
    mm_kernel<64, 64, 2><<<(n + 15) / 16, 128>>>(hb, Wg, t0, n, ats, atd);
    gat_agg<true><<<gW, 256>>>(t0, bg, out, Wl, bl, n);
}